// round 3
// baseline (speedup 1.0000x reference)
#include <cuda_runtime.h>
#include <math.h>

#define NS 30000
#define NG 3000
#define DD 128
#define KNN 16

// ---------------- scratch (no allocations allowed) ----------------
__device__ float  g_hs[NS * DD];
__device__ float  g_ms[NS * DD];
__device__ float  g_xsout[NS * DD];
__device__ float  g_hg[NG * DD];
__device__ float  g_mg[NG * DD];
__device__ float  g_xgout[NG * DD];
__device__ float  g_WcS[DD * DD];
__device__ float  g_WcG[DD * DD];
__device__ float4 g_ps4[NS];
__device__ int    g_idx[NG * KNN];
__device__ float  g_w[NG * KNN];

// ---------------- pos prep: pack (x,y,z,|s|^2) ----------------
// |s|^2 replicates XLA's (pos**2).sum(-1): plain rounded mul/add, NO fma.
__global__ void prep_pos_kernel(const float* __restrict__ pos_s) {
    int i = blockIdx.x * 256 + threadIdx.x;
    if (i < NS) {
        float x = pos_s[3 * i + 0];
        float y = pos_s[3 * i + 1];
        float z = pos_s[3 * i + 2];
        float s2 = __fadd_rn(__fadd_rn(__fmul_rn(x, x), __fmul_rn(y, y)),
                             __fmul_rn(z, z));
        g_ps4[i] = make_float4(x, y, z, s2);
    }
}

// ---------------- zero xs_out ----------------
__global__ void zero_xsout_kernel() {
    int i = blockIdx.x * 256 + threadIdx.x;         // one float4 per thread
    float4* p = reinterpret_cast<float4*>(g_xsout);
    if (i < (NS * DD) / 4) p[i] = make_float4(0.f, 0.f, 0.f, 0.f);
}

// ---------------- generic SIMT GEMM: C = act(A @ W) ----------------
template <int KT, bool TWO_A, bool RELU>
__global__ void __launch_bounds__(256) gemm_kernel(
    const float* __restrict__ A1, const float* __restrict__ A2,
    const float* __restrict__ Wa, const float* __restrict__ Wb,
    float* __restrict__ Ca, float* __restrict__ Cb, int M)
{
    const float* W = (blockIdx.y == 0) ? Wa : Wb;
    float* C       = (blockIdx.y == 0) ? Ca : Cb;

    __shared__ float As[32][132];   // [k][row], padded
    __shared__ float Ws[32][128];   // [k][col]

    const int t = threadIdx.x;
    const int rowBlock = blockIdx.x * 128;
    const int rb = (t / 16) * 8;    // row base
    const int cb = (t % 16) * 8;    // col base

    const int lr = t / 8;
    const int lk = (t % 8) * 4;
    const int wk = t / 32;
    const int wc = (t % 32) * 4;

    float acc[8][8] = {};

    for (int kt = 0; kt < KT / 32; ++kt) {
        const float* Asrc = (TWO_A && kt >= 4) ? A2 : A1;
        const int kb = (TWO_A && kt >= 4) ? (kt * 32 - 128) : (kt * 32);

        #pragma unroll
        for (int p = 0; p < 4; p++) {
            int r = lr + p * 32;
            int grow = rowBlock + r;
            float4 v = make_float4(0.f, 0.f, 0.f, 0.f);
            if (grow < M)
                v = *reinterpret_cast<const float4*>(&Asrc[grow * 128 + kb + lk]);
            As[lk + 0][r] = v.x;
            As[lk + 1][r] = v.y;
            As[lk + 2][r] = v.z;
            As[lk + 3][r] = v.w;
        }
        #pragma unroll
        for (int p = 0; p < 4; p++) {
            int k = wk + p * 8;
            *reinterpret_cast<float4*>(&Ws[k][wc]) =
                *reinterpret_cast<const float4*>(&W[(kt * 32 + k) * 128 + wc]);
        }
        __syncthreads();

        #pragma unroll
        for (int kk = 0; kk < 32; ++kk) {
            float a[8], b[8];
            *reinterpret_cast<float4*>(&a[0]) = *reinterpret_cast<float4*>(&As[kk][rb]);
            *reinterpret_cast<float4*>(&a[4]) = *reinterpret_cast<float4*>(&As[kk][rb + 4]);
            *reinterpret_cast<float4*>(&b[0]) = *reinterpret_cast<float4*>(&Ws[kk][cb]);
            *reinterpret_cast<float4*>(&b[4]) = *reinterpret_cast<float4*>(&Ws[kk][cb + 4]);
            #pragma unroll
            for (int i = 0; i < 8; i++)
                #pragma unroll
                for (int j = 0; j < 8; j++)
                    acc[i][j] = fmaf(a[i], b[j], acc[i][j]);
        }
        __syncthreads();
    }

    #pragma unroll
    for (int i = 0; i < 8; i++) {
        int grow = rowBlock + rb + i;
        if (grow < M) {
            float4 v0, v1;
            if (RELU) {
                v0 = make_float4(fmaxf(acc[i][0], 0.f), fmaxf(acc[i][1], 0.f),
                                 fmaxf(acc[i][2], 0.f), fmaxf(acc[i][3], 0.f));
                v1 = make_float4(fmaxf(acc[i][4], 0.f), fmaxf(acc[i][5], 0.f),
                                 fmaxf(acc[i][6], 0.f), fmaxf(acc[i][7], 0.f));
            } else {
                v0 = make_float4(acc[i][0], acc[i][1], acc[i][2], acc[i][3]);
                v1 = make_float4(acc[i][4], acc[i][5], acc[i][6], acc[i][7]);
            }
            *reinterpret_cast<float4*>(&C[grow * 128 + cb])     = v0;
            *reinterpret_cast<float4*>(&C[grow * 128 + cb + 4]) = v1;
        }
    }
}

// ---------------- kNN: one warp per graph node, reference-replicated d2 ----------------
// d2 = (g2 + s2) - 2*dot, dot = fma(gz,sz, fma(gy,sy, gx*sx))
// g2/s2 = ((x*x + y*y) + z*z) with plain rounded ops.
// Ties broken by lower index (matches jax top_k).
#define TILE 2048
__global__ void __launch_bounds__(256) knn_kernel(const float* __restrict__ pos_g) {
    __shared__ float4 tile[TILE];
    const int warp = threadIdx.x / 32;
    const int lane = threadIdx.x % 32;
    const int g = blockIdx.x * 8 + warp;

    const float gx = pos_g[g * 3 + 0];
    const float gy = pos_g[g * 3 + 1];
    const float gz = pos_g[g * 3 + 2];
    const float g2 = __fadd_rn(__fadd_rn(__fmul_rn(gx, gx), __fmul_rn(gy, gy)),
                               __fmul_rn(gz, gz));

    float bd[16];
    int   bi[16];
    #pragma unroll
    for (int i = 0; i < 16; i++) { bd[i] = 3.4e38f; bi[i] = 0x7fffffff; }
    float worst = 3.4e38f;
    int wslot = 0;

    for (int t0 = 0; t0 < NS; t0 += TILE) {
        int cnt = min(TILE, NS - t0);
        for (int i = threadIdx.x; i < cnt; i += 256) tile[i] = g_ps4[t0 + i];
        __syncthreads();

        for (int j = lane; j < cnt; j += 32) {
            float4 s = tile[j];
            float dot = __fmaf_rn(gz, s.z, __fmaf_rn(gy, s.y, __fmul_rn(gx, s.x)));
            float d2 = __fsub_rn(__fadd_rn(g2, s.w), __fmul_rn(2.0f, dot));
            if (d2 < worst) {
                int cand = t0 + j;
                #pragma unroll
                for (int i = 0; i < 16; i++)
                    if (i == wslot) { bd[i] = d2; bi[i] = cand; }
                // recompute worst slot (lex max on (d2, idx))
                worst = -3.4e38f; int widx = -1;
                #pragma unroll
                for (int i = 0; i < 16; i++)
                    if (bd[i] > worst || (bd[i] == worst && bi[i] > widx)) {
                        worst = bd[i]; widx = bi[i]; wslot = i;
                    }
            }
        }
        __syncthreads();
    }

    // warp merge: 16 rounds of lexicographic (d2, idx) argmin over 32x16 slots
    for (int r = 0; r < 16; r++) {
        float m = 3.4e38f; int mi = 0x7fffffff; int ms = 0;
        #pragma unroll
        for (int i = 0; i < 16; i++)
            if (bd[i] < m || (bd[i] == m && bi[i] < mi)) { m = bd[i]; mi = bi[i]; ms = i; }

        float bm = m; int bidx = mi;
        #pragma unroll
        for (int off = 16; off > 0; off >>= 1) {
            float om = __shfl_xor_sync(0xffffffffu, bm, off);
            int   oi = __shfl_xor_sync(0xffffffffu, bidx, off);
            if (om < bm || (om == bm && oi < bidx)) { bm = om; bidx = oi; }
        }

        // owner lane clears its winning slot (idx unique -> exactly one owner)
        if (m == bm && mi == bidx) {
            #pragma unroll
            for (int i = 0; i < 16; i++)
                if (i == ms) { bd[i] = 3.4e38f; bi[i] = 0x7fffffff; }
        }
        if (lane == 0) {
            g_idx[g * 16 + r] = bidx;
            // w = exp(neg_d2 / 12.5), neg_d2 = -d2 (exact), division rounded
            g_w[g * 16 + r] = expf(__fdiv_rn(-bm, 12.5f));
        }
    }
}

// ---------------- scatter: xs_out[idx[g,j]] += mg[g] * w[g,j] ----------------
__global__ void __launch_bounds__(128) scatter_kernel() {
    const int g = blockIdx.x;
    const int t = threadIdx.x;
    __shared__ int   sidx[16];
    __shared__ float sw[16];
    if (t < 16) { sidx[t] = g_idx[g * 16 + t]; sw[t] = g_w[g * 16 + t]; }
    __syncthreads();
    float v = g_mg[g * 128 + t];
    #pragma unroll
    for (int j = 0; j < 16; j++)
        atomicAdd(&g_xsout[sidx[j] * 128 + t], v * sw[j]);
}

// ---------------- gather: xg_out[g] = sum_j ms[idx[g,j]] * w[g,j] ----------------
__global__ void __launch_bounds__(128) gather_kernel() {
    const int g = blockIdx.x;
    const int t = threadIdx.x;
    __shared__ int   sidx[16];
    __shared__ float sw[16];
    if (t < 16) { sidx[t] = g_idx[g * 16 + t]; sw[t] = g_w[g * 16 + t]; }
    __syncthreads();
    float acc = 0.f;
    #pragma unroll
    for (int j = 0; j < 16; j++)
        acc = fmaf(g_ms[sidx[j] * 128 + t], sw[j], acc);
    g_xgout[g * 128 + t] = acc;
}

// ---------------- launch ----------------
extern "C" void kernel_launch(void* const* d_in, const int* in_sizes, int n_in,
                              void* d_out, int out_size)
{
    const float* xs       = (const float*)d_in[0];
    const float* xg       = (const float*)d_in[1];
    const float* pos_s    = (const float*)d_in[2];
    const float* pos_g    = (const float*)d_in[3];
    const float* W_s_pre  = (const float*)d_in[4];
    const float* W_g_pre  = (const float*)d_in[5];
    const float* W_gs     = (const float*)d_in[6];
    const float* W_sg     = (const float*)d_in[7];
    const float* W_s_post = (const float*)d_in[8];
    const float* W_g_post = (const float*)d_in[9];
    float* out = (float*)d_out;
    float* out_s = out;                 // xs_new: 30000 x 128
    float* out_g = out + NS * DD;       // xg_new: 3000 x 128

    prep_pos_kernel<<<(NS + 255) / 256, 256>>>(pos_s);

    // combined weights: WcS = W_s_pre @ W_sg, WcG = W_g_pre @ W_gs
    {
        float* WcS; cudaGetSymbolAddress((void**)&WcS, g_WcS);
        float* WcG; cudaGetSymbolAddress((void**)&WcG, g_WcG);
        gemm_kernel<128, false, false><<<dim3(1, 1), 256>>>(
            W_s_pre, nullptr, W_sg, W_sg, WcS, WcS, 128);
        gemm_kernel<128, false, false><<<dim3(1, 1), 256>>>(
            W_g_pre, nullptr, W_gs, W_gs, WcG, WcG, 128);
    }

    knn_kernel<<<NG / 8, 256>>>(pos_g);

    zero_xsout_kernel<<<(NS * DD / 4 + 255) / 256, 256>>>();

    {
        float* hs; cudaGetSymbolAddress((void**)&hs, g_hs);
        float* ms; cudaGetSymbolAddress((void**)&ms, g_ms);
        float* hg; cudaGetSymbolAddress((void**)&hg, g_hg);
        float* mg; cudaGetSymbolAddress((void**)&mg, g_mg);
        float* WcS; cudaGetSymbolAddress((void**)&WcS, g_WcS);
        float* WcG; cudaGetSymbolAddress((void**)&WcG, g_WcG);
        gemm_kernel<128, false, false><<<dim3((NS + 127) / 128, 2), 256>>>(
            xs, nullptr, W_s_pre, WcS, hs, ms, NS);
        gemm_kernel<128, false, false><<<dim3((NG + 127) / 128, 2), 256>>>(
            xg, nullptr, W_g_pre, WcG, hg, mg, NG);
    }

    scatter_kernel<<<NG, 128>>>();
    gather_kernel<<<NG, 128>>>();

    {
        float* hs; cudaGetSymbolAddress((void**)&hs, g_hs);
        float* hg; cudaGetSymbolAddress((void**)&hg, g_hg);
        float* xso; cudaGetSymbolAddress((void**)&xso, g_xsout);
        float* xgo; cudaGetSymbolAddress((void**)&xgo, g_xgout);
        gemm_kernel<256, true, true><<<dim3((NS + 127) / 128, 1), 256>>>(
            hs, xso, W_s_post, W_s_post, out_s, out_s, NS);
        gemm_kernel<256, true, true><<<dim3((NG + 127) / 128, 1), 256>>>(
            hg, xgo, W_g_post, W_g_post, out_g, out_g, NG);
    }
}

// round 4
// speedup vs baseline: 1.7363x; 1.7363x over previous
#include <cuda_runtime.h>
#include <math.h>

#define NS 30000
#define NG 3000
#define DD 128
#define KNN 16

// ---------------- scratch (no allocations allowed) ----------------
__device__ float  g_hs[NS * DD];
__device__ float  g_ms[NS * DD];
__device__ float  g_xsout[NS * DD];
__device__ float  g_hg[NG * DD];
__device__ float  g_mg[NG * DD];
__device__ float  g_xgout[NG * DD];
__device__ float  g_WcS[DD * DD];
__device__ float  g_WcG[DD * DD];
__device__ float4 g_ps4[NS];
__device__ int    g_idx[NG * KNN];
__device__ float  g_w[NG * KNN];

// ---------------- pos prep: pack (x,y,z,|s|^2) ----------------
// |s|^2 replicates XLA's (pos**2).sum(-1): plain rounded mul/add, NO fma.
__global__ void prep_pos_kernel(const float* __restrict__ pos_s) {
    int i = blockIdx.x * 256 + threadIdx.x;
    if (i < NS) {
        float x = pos_s[3 * i + 0];
        float y = pos_s[3 * i + 1];
        float z = pos_s[3 * i + 2];
        float s2 = __fadd_rn(__fadd_rn(__fmul_rn(x, x), __fmul_rn(y, y)),
                             __fmul_rn(z, z));
        g_ps4[i] = make_float4(x, y, z, s2);
    }
}

// ---------------- zero xs_out ----------------
__global__ void zero_xsout_kernel() {
    int i = blockIdx.x * 256 + threadIdx.x;
    float4* p = reinterpret_cast<float4*>(g_xsout);
    if (i < (NS * DD) / 4) p[i] = make_float4(0.f, 0.f, 0.f, 0.f);
}

// ---------------- generic SIMT GEMM: C = act(A @ W) ----------------
template <int KT, bool TWO_A, bool RELU>
__global__ void __launch_bounds__(256) gemm_kernel(
    const float* __restrict__ A1, const float* __restrict__ A2,
    const float* __restrict__ Wa, const float* __restrict__ Wb,
    float* __restrict__ Ca, float* __restrict__ Cb, int M)
{
    const float* W = (blockIdx.y == 0) ? Wa : Wb;
    float* C       = (blockIdx.y == 0) ? Ca : Cb;

    __shared__ float As[32][132];
    __shared__ float Ws[32][128];

    const int t = threadIdx.x;
    const int rowBlock = blockIdx.x * 128;
    const int rb = (t / 16) * 8;
    const int cb = (t % 16) * 8;

    const int lr = t / 8;
    const int lk = (t % 8) * 4;
    const int wk = t / 32;
    const int wc = (t % 32) * 4;

    float acc[8][8] = {};

    for (int kt = 0; kt < KT / 32; ++kt) {
        const float* Asrc = (TWO_A && kt >= 4) ? A2 : A1;
        const int kb = (TWO_A && kt >= 4) ? (kt * 32 - 128) : (kt * 32);

        #pragma unroll
        for (int p = 0; p < 4; p++) {
            int r = lr + p * 32;
            int grow = rowBlock + r;
            float4 v = make_float4(0.f, 0.f, 0.f, 0.f);
            if (grow < M)
                v = *reinterpret_cast<const float4*>(&Asrc[grow * 128 + kb + lk]);
            As[lk + 0][r] = v.x;
            As[lk + 1][r] = v.y;
            As[lk + 2][r] = v.z;
            As[lk + 3][r] = v.w;
        }
        #pragma unroll
        for (int p = 0; p < 4; p++) {
            int k = wk + p * 8;
            *reinterpret_cast<float4*>(&Ws[k][wc]) =
                *reinterpret_cast<const float4*>(&W[(kt * 32 + k) * 128 + wc]);
        }
        __syncthreads();

        #pragma unroll
        for (int kk = 0; kk < 32; ++kk) {
            float a[8], b[8];
            *reinterpret_cast<float4*>(&a[0]) = *reinterpret_cast<float4*>(&As[kk][rb]);
            *reinterpret_cast<float4*>(&a[4]) = *reinterpret_cast<float4*>(&As[kk][rb + 4]);
            *reinterpret_cast<float4*>(&b[0]) = *reinterpret_cast<float4*>(&Ws[kk][cb]);
            *reinterpret_cast<float4*>(&b[4]) = *reinterpret_cast<float4*>(&Ws[kk][cb + 4]);
            #pragma unroll
            for (int i = 0; i < 8; i++)
                #pragma unroll
                for (int j = 0; j < 8; j++)
                    acc[i][j] = fmaf(a[i], b[j], acc[i][j]);
        }
        __syncthreads();
    }

    #pragma unroll
    for (int i = 0; i < 8; i++) {
        int grow = rowBlock + rb + i;
        if (grow < M) {
            float4 v0, v1;
            if (RELU) {
                v0 = make_float4(fmaxf(acc[i][0], 0.f), fmaxf(acc[i][1], 0.f),
                                 fmaxf(acc[i][2], 0.f), fmaxf(acc[i][3], 0.f));
                v1 = make_float4(fmaxf(acc[i][4], 0.f), fmaxf(acc[i][5], 0.f),
                                 fmaxf(acc[i][6], 0.f), fmaxf(acc[i][7], 0.f));
            } else {
                v0 = make_float4(acc[i][0], acc[i][1], acc[i][2], acc[i][3]);
                v1 = make_float4(acc[i][4], acc[i][5], acc[i][6], acc[i][7]);
            }
            *reinterpret_cast<float4*>(&C[grow * 128 + cb])     = v0;
            *reinterpret_cast<float4*>(&C[grow * 128 + cb + 4]) = v1;
        }
    }
}

// ---------------- kNN: filter-then-select with warp-shared threshold ----------------
// Hot loop: LDS.128 + bit-exact d2 + ballot append. Selection happens only on
// rare buffer rebuilds (expected ~2-3 per graph node).
// d2 = (g2 + s2) - 2*dot, dot = fma(gz,sz, fma(gy,sy, gx*sx))  (reference-replicated)
// Lex (d2, idx) ordering matches jax top_k tie-breaking.
#define TILE   1024
#define BUFCAP 272           // 16 kept + up to 256 pending appends
#define WPB    8             // warps per block

// warp-local selection: pick the lex-(d,idx)-smallest 16 of buf[0..cnt),
// write them (in order) via emit callback semantics. Returns 16th d (new T).
__device__ __forceinline__ float warp_select16(
    float* bd, int* bi, int cnt, int lane,
    float* outd, int* outi)           // outd/outi: 16-entry arrays (shared)
{
    float last = 3.4e38f;
    for (int r = 0; r < 16; r++) {
        // local lex argmin
        float md = 3.4e38f; int mi = 0x7fffffff; int mp = -1;
        for (int i = lane; i < cnt; i += 32) {
            float d = bd[i]; int ix = bi[i];
            if (d < md || (d == md && ix < mi)) { md = d; mi = ix; mp = i; }
        }
        // warp lex reduce
        float gd = md; int gi = mi;
        #pragma unroll
        for (int off = 16; off > 0; off >>= 1) {
            float od = __shfl_xor_sync(0xffffffffu, gd, off);
            int   oi = __shfl_xor_sync(0xffffffffu, gi, off);
            if (od < gd || (od == gd && oi < gi)) { gd = od; gi = oi; }
        }
        // owner marks its slot removed (idx unique -> exactly one owner)
        if (md == gd && mi == gi && mp >= 0) {
            bd[mp] = 3.4e38f; bi[mp] = 0x7fffffff;
        }
        if (lane == 0) { outd[r] = gd; outi[r] = gi; }
        last = gd;
    }
    return last;   // 16th smallest (warp-uniform)
}

__global__ void __launch_bounds__(256) knn_kernel(const float* __restrict__ pos_g) {
    __shared__ float4 tile[TILE];
    __shared__ float  bufd[WPB][BUFCAP];
    __shared__ int    bufi[WPB][BUFCAP];
    __shared__ float  keepd[WPB][16];
    __shared__ int    keepi[WPB][16];

    const int warp = threadIdx.x / 32;
    const int lane = threadIdx.x % 32;
    const int g = blockIdx.x * WPB + warp;

    const float gx = pos_g[g * 3 + 0];
    const float gy = pos_g[g * 3 + 1];
    const float gz = pos_g[g * 3 + 2];
    const float g2 = __fadd_rn(__fadd_rn(__fmul_rn(gx, gx), __fmul_rn(gy, gy)),
                               __fmul_rn(gz, gz));

    float* bd = bufd[warp];
    int*   bi = bufi[warp];
    float T = 3.4e38f;
    int cnt = 0;

    for (int t0 = 0; t0 < NS; t0 += TILE) {
        const int cntT = min(TILE, NS - t0);
        for (int i = threadIdx.x; i < cntT; i += 256) tile[i] = g_ps4[t0 + i];
        __syncthreads();

        for (int j0 = 0; j0 < cntT; j0 += 32) {
            const int j = j0 + lane;
            const bool valid = (j < cntT);
            float4 s = tile[valid ? j : 0];
            float dot = __fmaf_rn(gz, s.z, __fmaf_rn(gy, s.y, __fmul_rn(gx, s.x)));
            float d2 = __fsub_rn(__fadd_rn(g2, s.w), __fmul_rn(2.0f, dot));
            const bool p = valid && (d2 < T);
            const unsigned m = __ballot_sync(0xffffffffu, p);
            if (m) {
                const int pos = cnt + __popc(m & ((1u << lane) - 1u));
                if (p) { bd[pos] = d2; bi[pos] = t0 + j; }
                cnt += __popc(m);
                if (cnt > BUFCAP - 32) {
                    T = warp_select16(bd, bi, cnt, lane, keepd[warp], keepi[warp]);
                    // compact kept 16 to front
                    if (lane < 16) { bd[lane] = keepd[warp][lane]; bi[lane] = keepi[warp][lane]; }
                    __syncwarp();
                    cnt = 16;
                }
            }
        }
        __syncthreads();
    }

    // final selection + emit
    warp_select16(bd, bi, cnt, lane, keepd[warp], keepi[warp]);
    if (lane < 16) {
        float d = keepd[warp][lane];
        g_idx[g * 16 + lane] = keepi[warp][lane];
        g_w[g * 16 + lane]   = expf(__fdiv_rn(-d, 12.5f));
    }
}

// ---------------- scatter: xs_out[idx[g,j]] += mg[g] * w[g,j] ----------------
__global__ void __launch_bounds__(128) scatter_kernel() {
    const int g = blockIdx.x;
    const int t = threadIdx.x;
    __shared__ int   sidx[16];
    __shared__ float sw[16];
    if (t < 16) { sidx[t] = g_idx[g * 16 + t]; sw[t] = g_w[g * 16 + t]; }
    __syncthreads();
    float v = g_mg[g * 128 + t];
    #pragma unroll
    for (int j = 0; j < 16; j++)
        atomicAdd(&g_xsout[sidx[j] * 128 + t], v * sw[j]);
}

// ---------------- gather: xg_out[g] = sum_j ms[idx[g,j]] * w[g,j] ----------------
__global__ void __launch_bounds__(128) gather_kernel() {
    const int g = blockIdx.x;
    const int t = threadIdx.x;
    __shared__ int   sidx[16];
    __shared__ float sw[16];
    if (t < 16) { sidx[t] = g_idx[g * 16 + t]; sw[t] = g_w[g * 16 + t]; }
    __syncthreads();
    float acc = 0.f;
    #pragma unroll
    for (int j = 0; j < 16; j++)
        acc = fmaf(g_ms[sidx[j] * 128 + t], sw[j], acc);
    g_xgout[g * 128 + t] = acc;
}

// ---------------- launch ----------------
extern "C" void kernel_launch(void* const* d_in, const int* in_sizes, int n_in,
                              void* d_out, int out_size)
{
    const float* xs       = (const float*)d_in[0];
    const float* xg       = (const float*)d_in[1];
    const float* pos_s    = (const float*)d_in[2];
    const float* pos_g    = (const float*)d_in[3];
    const float* W_s_pre  = (const float*)d_in[4];
    const float* W_g_pre  = (const float*)d_in[5];
    const float* W_gs     = (const float*)d_in[6];
    const float* W_sg     = (const float*)d_in[7];
    const float* W_s_post = (const float*)d_in[8];
    const float* W_g_post = (const float*)d_in[9];
    float* out = (float*)d_out;
    float* out_s = out;                 // xs_new: 30000 x 128
    float* out_g = out + NS * DD;       // xg_new: 3000 x 128

    prep_pos_kernel<<<(NS + 255) / 256, 256>>>(pos_s);

    // combined weights: WcS = W_s_pre @ W_sg, WcG = W_g_pre @ W_gs
    {
        float* WcS; cudaGetSymbolAddress((void**)&WcS, g_WcS);
        float* WcG; cudaGetSymbolAddress((void**)&WcG, g_WcG);
        gemm_kernel<128, false, false><<<dim3(1, 1), 256>>>(
            W_s_pre, nullptr, W_sg, W_sg, WcS, WcS, 128);
        gemm_kernel<128, false, false><<<dim3(1, 1), 256>>>(
            W_g_pre, nullptr, W_gs, W_gs, WcG, WcG, 128);
    }

    knn_kernel<<<NG / WPB, 256>>>(pos_g);

    zero_xsout_kernel<<<(NS * DD / 4 + 255) / 256, 256>>>();

    {
        float* hs; cudaGetSymbolAddress((void**)&hs, g_hs);
        float* ms; cudaGetSymbolAddress((void**)&ms, g_ms);
        float* hg; cudaGetSymbolAddress((void**)&hg, g_hg);
        float* mg; cudaGetSymbolAddress((void**)&mg, g_mg);
        float* WcS; cudaGetSymbolAddress((void**)&WcS, g_WcS);
        float* WcG; cudaGetSymbolAddress((void**)&WcG, g_WcG);
        gemm_kernel<128, false, false><<<dim3((NS + 127) / 128, 2), 256>>>(
            xs, nullptr, W_s_pre, WcS, hs, ms, NS);
        gemm_kernel<128, false, false><<<dim3((NG + 127) / 128, 2), 256>>>(
            xg, nullptr, W_g_pre, WcG, hg, mg, NG);
    }

    scatter_kernel<<<NG, 128>>>();
    gather_kernel<<<NG, 128>>>();

    {
        float* hs; cudaGetSymbolAddress((void**)&hs, g_hs);
        float* hg; cudaGetSymbolAddress((void**)&hg, g_hg);
        float* xso; cudaGetSymbolAddress((void**)&xso, g_xsout);
        float* xgo; cudaGetSymbolAddress((void**)&xgo, g_xgout);
        gemm_kernel<256, true, true><<<dim3((NS + 127) / 128, 1), 256>>>(
            hs, xso, W_s_post, W_s_post, out_s, out_s, NS);
        gemm_kernel<256, true, true><<<dim3((NG + 127) / 128, 1), 256>>>(
            hg, xgo, W_g_post, W_g_post, out_g, out_g, NG);
    }
}

// round 6
// speedup vs baseline: 2.5463x; 1.4665x over previous
#include <cuda_runtime.h>
#include <math.h>

#define NS 30000
#define NG 3000
#define DD 128
#define KNN 16

#define NCELL1 8
#define NCELLS (NCELL1 * NCELL1 * NCELL1)
#define CELL_INV (NCELL1 / 60.0f)     // cells span the 60 A box
#define R2_CERT (7.5f * 7.5f)         // guaranteed coverage radius^2

// ---------------- scratch (no allocations allowed) ----------------
__device__ float  g_hs[NS * DD];
__device__ float  g_ms[NS * DD];
__device__ float  g_xsout[NS * DD];
__device__ float  g_hg[NG * DD];
__device__ float  g_mg[NG * DD];
__device__ float  g_xgout[NG * DD];
__device__ float  g_WcS[DD * DD];
__device__ float  g_WcG[DD * DD];
__device__ float4 g_ps4[NS];          // (x,y,z,|s|^2) in original order
__device__ float4 g_cs4[NS];          // cell-sorted copy
__device__ int    g_ci[NS];           // cell-sorted original index
__device__ int    g_cellcnt[NCELLS];
__device__ int    g_cellstart[NCELLS + 1];
__device__ int    g_cellcur[NCELLS];
__device__ int    g_idx[NG * KNN];
__device__ float  g_w[NG * KNN];

__device__ __forceinline__ int cell_of(float x, float y, float z) {
    int cx = min(NCELL1 - 1, max(0, (int)(x * CELL_INV)));
    int cy = min(NCELL1 - 1, max(0, (int)(y * CELL_INV)));
    int cz = min(NCELL1 - 1, max(0, (int)(z * CELL_INV)));
    return (cz * NCELL1 + cy) * NCELL1 + cx;
}

// ---------------- pos prep: pack (x,y,z,|s|^2) ----------------
// |s|^2 replicates XLA's (pos**2).sum(-1): plain rounded mul/add, NO fma.
__global__ void prep_pos_kernel(const float* __restrict__ pos_s) {
    int i = blockIdx.x * 256 + threadIdx.x;
    if (i < NS) {
        float x = pos_s[3 * i + 0];
        float y = pos_s[3 * i + 1];
        float z = pos_s[3 * i + 2];
        float s2 = __fadd_rn(__fadd_rn(__fmul_rn(x, x), __fmul_rn(y, y)),
                             __fmul_rn(z, z));
        g_ps4[i] = make_float4(x, y, z, s2);
    }
}

// ---------------- cell binning ----------------
__global__ void cell_zero_kernel() {
    int i = blockIdx.x * 256 + threadIdx.x;
    if (i < NCELLS) g_cellcnt[i] = 0;
}

__global__ void cell_count_kernel() {
    int i = blockIdx.x * 256 + threadIdx.x;
    if (i < NS) {
        float4 p = g_ps4[i];
        atomicAdd(&g_cellcnt[cell_of(p.x, p.y, p.z)], 1);
    }
}

__global__ void __launch_bounds__(NCELLS) cell_prefix_kernel() {
    __shared__ int tmp[NCELLS];
    int t = threadIdx.x;
    int v = g_cellcnt[t];
    tmp[t] = v;
    __syncthreads();
    for (int off = 1; off < NCELLS; off <<= 1) {
        int add = (t >= off) ? tmp[t - off] : 0;
        __syncthreads();
        tmp[t] += add;
        __syncthreads();
    }
    g_cellstart[t] = tmp[t] - v;      // exclusive
    g_cellcur[t]   = tmp[t] - v;
    if (t == NCELLS - 1) g_cellstart[NCELLS] = tmp[t];
}

__global__ void cell_scatter_kernel() {
    int i = blockIdx.x * 256 + threadIdx.x;
    if (i < NS) {
        float4 p = g_ps4[i];
        int slot = atomicAdd(&g_cellcur[cell_of(p.x, p.y, p.z)], 1);
        g_cs4[slot] = p;
        g_ci[slot]  = i;
    }
}

// ---------------- zero xs_out ----------------
__global__ void zero_xsout_kernel() {
    int i = blockIdx.x * 256 + threadIdx.x;
    float4* p = reinterpret_cast<float4*>(g_xsout);
    if (i < (NS * DD) / 4) p[i] = make_float4(0.f, 0.f, 0.f, 0.f);
}

// ---------------- generic SIMT GEMM: C = act(A @ W) ----------------
template <int KT, bool TWO_A, bool RELU>
__global__ void __launch_bounds__(256) gemm_kernel(
    const float* __restrict__ A1, const float* __restrict__ A2,
    const float* __restrict__ Wa, const float* __restrict__ Wb,
    float* __restrict__ Ca, float* __restrict__ Cb, int M)
{
    const float* W = (blockIdx.y == 0) ? Wa : Wb;
    float* C       = (blockIdx.y == 0) ? Ca : Cb;

    __shared__ float As[32][132];
    __shared__ float Ws[32][128];

    const int t = threadIdx.x;
    const int rowBlock = blockIdx.x * 128;
    const int rb = (t / 16) * 8;
    const int cb = (t % 16) * 8;

    const int lr = t / 8;
    const int lk = (t % 8) * 4;
    const int wk = t / 32;
    const int wc = (t % 32) * 4;

    float acc[8][8] = {};

    for (int kt = 0; kt < KT / 32; ++kt) {
        const float* Asrc = (TWO_A && kt >= 4) ? A2 : A1;
        const int kb = (TWO_A && kt >= 4) ? (kt * 32 - 128) : (kt * 32);

        #pragma unroll
        for (int p = 0; p < 4; p++) {
            int r = lr + p * 32;
            int grow = rowBlock + r;
            float4 v = make_float4(0.f, 0.f, 0.f, 0.f);
            if (grow < M)
                v = *reinterpret_cast<const float4*>(&Asrc[grow * 128 + kb + lk]);
            As[lk + 0][r] = v.x;
            As[lk + 1][r] = v.y;
            As[lk + 2][r] = v.z;
            As[lk + 3][r] = v.w;
        }
        #pragma unroll
        for (int p = 0; p < 4; p++) {
            int k = wk + p * 8;
            *reinterpret_cast<float4*>(&Ws[k][wc]) =
                *reinterpret_cast<const float4*>(&W[(kt * 32 + k) * 128 + wc]);
        }
        __syncthreads();

        #pragma unroll
        for (int kk = 0; kk < 32; ++kk) {
            float a[8], b[8];
            *reinterpret_cast<float4*>(&a[0]) = *reinterpret_cast<float4*>(&As[kk][rb]);
            *reinterpret_cast<float4*>(&a[4]) = *reinterpret_cast<float4*>(&As[kk][rb + 4]);
            *reinterpret_cast<float4*>(&b[0]) = *reinterpret_cast<float4*>(&Ws[kk][cb]);
            *reinterpret_cast<float4*>(&b[4]) = *reinterpret_cast<float4*>(&Ws[kk][cb + 4]);
            #pragma unroll
            for (int i = 0; i < 8; i++)
                #pragma unroll
                for (int j = 0; j < 8; j++)
                    acc[i][j] = fmaf(a[i], b[j], acc[i][j]);
        }
        __syncthreads();
    }

    #pragma unroll
    for (int i = 0; i < 8; i++) {
        int grow = rowBlock + rb + i;
        if (grow < M) {
            float4 v0, v1;
            if (RELU) {
                v0 = make_float4(fmaxf(acc[i][0], 0.f), fmaxf(acc[i][1], 0.f),
                                 fmaxf(acc[i][2], 0.f), fmaxf(acc[i][3], 0.f));
                v1 = make_float4(fmaxf(acc[i][4], 0.f), fmaxf(acc[i][5], 0.f),
                                 fmaxf(acc[i][6], 0.f), fmaxf(acc[i][7], 0.f));
            } else {
                v0 = make_float4(acc[i][0], acc[i][1], acc[i][2], acc[i][3]);
                v1 = make_float4(acc[i][4], acc[i][5], acc[i][6], acc[i][7]);
            }
            *reinterpret_cast<float4*>(&C[grow * 128 + cb])     = v0;
            *reinterpret_cast<float4*>(&C[grow * 128 + cb + 4]) = v1;
        }
    }
}

// ---------------- kNN over cell grid ----------------
// d2 = (g2 + s2) - 2*dot, dot = fma(gz,sz, fma(gy,sy, gx*sx))  (reference-replicated)
// Exact lex-(d2,idx) top-16 over the 3x3x3 cell candidate set, certified by
// d16 <= 7.5^2 (region covers all points within 7.5A of g). On certification
// failure: exact full scan fallback.
#define BUFCAP 288
#define WPB    8

__device__ __forceinline__ float warp_select16(
    float* bd, int* bi, int cnt, int lane,
    float* outd, int* outi)
{
    float last = 3.4e38f;
    for (int r = 0; r < 16; r++) {
        float md = 3.4e38f; int mi = 0x7fffffff; int mp = -1;
        for (int i = lane; i < cnt; i += 32) {
            float d = bd[i]; int ix = bi[i];
            if (d < md || (d == md && ix < mi)) { md = d; mi = ix; mp = i; }
        }
        float gd = md; int gi = mi;
        #pragma unroll
        for (int off = 16; off > 0; off >>= 1) {
            float od = __shfl_xor_sync(0xffffffffu, gd, off);
            int   oi = __shfl_xor_sync(0xffffffffu, gi, off);
            if (od < gd || (od == gd && oi < gi)) { gd = od; gi = oi; }
        }
        if (md == gd && mi == gi && mp >= 0) {
            bd[mp] = 3.4e38f; bi[mp] = 0x7fffffff;
        }
        if (lane == 0) { outd[r] = gd; outi[r] = gi; }
        last = gd;
    }
    return last;
}

__global__ void __launch_bounds__(32 * WPB) knn_kernel(const float* __restrict__ pos_g) {
    __shared__ float  bufd[WPB][BUFCAP];
    __shared__ int    bufi[WPB][BUFCAP];
    __shared__ float  keepd[WPB][16];
    __shared__ int    keepi[WPB][16];

    const int warp = threadIdx.x / 32;
    const int lane = threadIdx.x % 32;
    const int g = blockIdx.x * WPB + warp;

    const float gx = pos_g[g * 3 + 0];
    const float gy = pos_g[g * 3 + 1];
    const float gz = pos_g[g * 3 + 2];
    const float g2 = __fadd_rn(__fadd_rn(__fmul_rn(gx, gx), __fmul_rn(gy, gy)),
                               __fmul_rn(gz, gz));

    const int cx = min(NCELL1 - 1, max(0, (int)(gx * CELL_INV)));
    const int cy = min(NCELL1 - 1, max(0, (int)(gy * CELL_INV)));
    const int cz = min(NCELL1 - 1, max(0, (int)(gz * CELL_INV)));

    float* bd = bufd[warp];
    int*   bi = bufi[warp];
    float T = 3.4e38f;
    int cnt = 0;
    int ncand = 0;

    const int z0 = max(0, cz - 1), z1 = min(NCELL1 - 1, cz + 1);
    const int y0 = max(0, cy - 1), y1 = min(NCELL1 - 1, cy + 1);
    const int x0 = max(0, cx - 1), x1 = min(NCELL1 - 1, cx + 1);

    for (int zz = z0; zz <= z1; zz++)
    for (int yy = y0; yy <= y1; yy++)
    for (int xx = x0; xx <= x1; xx++) {
        const int c = (zz * NCELL1 + yy) * NCELL1 + xx;
        const int s = g_cellstart[c];
        const int e = g_cellstart[c + 1];
        ncand += e - s;
        for (int j0 = s; j0 < e; j0 += 32) {
            const int j = j0 + lane;
            const bool valid = (j < e);
            float4 p = g_cs4[valid ? j : s];
            float dot = __fmaf_rn(gz, p.z, __fmaf_rn(gy, p.y, __fmul_rn(gx, p.x)));
            float d2 = __fsub_rn(__fadd_rn(g2, p.w), __fmul_rn(2.0f, dot));
            const bool pr = valid && (d2 < T);
            const unsigned m = __ballot_sync(0xffffffffu, pr);
            if (m) {
                const int pos = cnt + __popc(m & ((1u << lane) - 1u));
                if (pr) { bd[pos] = d2; bi[pos] = g_ci[j]; }
                cnt += __popc(m);
                if (cnt > BUFCAP - 32) {
                    T = warp_select16(bd, bi, cnt, lane, keepd[warp], keepi[warp]);
                    if (lane < 16) { bd[lane] = keepd[warp][lane]; bi[lane] = keepi[warp][lane]; }
                    __syncwarp();
                    cnt = 16;
                }
            }
        }
    }

    float d16 = warp_select16(bd, bi, cnt, lane, keepd[warp], keepi[warp]);

    // certification: top-16 is global iff 16th distance within guaranteed
    // coverage radius of the 3x3x3 region (and we saw >= 16 candidates)
    if (ncand < 16 || d16 > R2_CERT) {
        // exact fallback: full scan of all surface points
        T = 3.4e38f;
        cnt = 0;
        for (int j0 = 0; j0 < NS; j0 += 32) {
            const int j = j0 + lane;
            const bool valid = (j < NS);
            float4 p = g_ps4[valid ? j : 0];
            float dot = __fmaf_rn(gz, p.z, __fmaf_rn(gy, p.y, __fmul_rn(gx, p.x)));
            float d2 = __fsub_rn(__fadd_rn(g2, p.w), __fmul_rn(2.0f, dot));
            const bool pr = valid && (d2 < T);
            const unsigned m = __ballot_sync(0xffffffffu, pr);
            if (m) {
                const int pos = cnt + __popc(m & ((1u << lane) - 1u));
                if (pr) { bd[pos] = d2; bi[pos] = j; }
                cnt += __popc(m);
                if (cnt > BUFCAP - 32) {
                    T = warp_select16(bd, bi, cnt, lane, keepd[warp], keepi[warp]);
                    if (lane < 16) { bd[lane] = keepd[warp][lane]; bi[lane] = keepi[warp][lane]; }
                    __syncwarp();
                    cnt = 16;
                }
            }
        }
        warp_select16(bd, bi, cnt, lane, keepd[warp], keepi[warp]);
    }

    if (lane < 16) {
        float d = keepd[warp][lane];
        g_idx[g * 16 + lane] = keepi[warp][lane];
        g_w[g * 16 + lane]   = expf(__fdiv_rn(-d, 12.5f));
    }
}

// ---------------- scatter: xs_out[idx[g,j]] += mg[g] * w[g,j] ----------------
__global__ void __launch_bounds__(128) scatter_kernel() {
    const int g = blockIdx.x;
    const int t = threadIdx.x;
    __shared__ int   sidx[16];
    __shared__ float sw[16];
    if (t < 16) { sidx[t] = g_idx[g * 16 + t]; sw[t] = g_w[g * 16 + t]; }
    __syncthreads();
    float v = g_mg[g * 128 + t];
    #pragma unroll
    for (int j = 0; j < 16; j++)
        atomicAdd(&g_xsout[sidx[j] * 128 + t], v * sw[j]);
}

// ---------------- gather: xg_out[g] = sum_j ms[idx[g,j]] * w[g,j] ----------------
__global__ void __launch_bounds__(128) gather_kernel() {
    const int g = blockIdx.x;
    const int t = threadIdx.x;
    __shared__ int   sidx[16];
    __shared__ float sw[16];
    if (t < 16) { sidx[t] = g_idx[g * 16 + t]; sw[t] = g_w[g * 16 + t]; }
    __syncthreads();
    float acc = 0.f;
    #pragma unroll
    for (int j = 0; j < 16; j++)
        acc = fmaf(g_ms[sidx[j] * 128 + t], sw[j], acc);
    g_xgout[g * 128 + t] = acc;
}

// ---------------- launch ----------------
extern "C" void kernel_launch(void* const* d_in, const int* in_sizes, int n_in,
                              void* d_out, int out_size)
{
    const float* xs       = (const float*)d_in[0];
    const float* xg       = (const float*)d_in[1];
    const float* pos_s    = (const float*)d_in[2];
    const float* pos_g    = (const float*)d_in[3];
    const float* W_s_pre  = (const float*)d_in[4];
    const float* W_g_pre  = (const float*)d_in[5];
    const float* W_gs     = (const float*)d_in[6];
    const float* W_sg     = (const float*)d_in[7];
    const float* W_s_post = (const float*)d_in[8];
    const float* W_g_post = (const float*)d_in[9];
    float* out = (float*)d_out;
    float* out_s = out;                 // xs_new: 30000 x 128
    float* out_g = out + NS * DD;       // xg_new: 3000 x 128

    prep_pos_kernel<<<(NS + 255) / 256, 256>>>(pos_s);

    // cell binning
    cell_zero_kernel<<<(NCELLS + 255) / 256, 256>>>();
    cell_count_kernel<<<(NS + 255) / 256, 256>>>();
    cell_prefix_kernel<<<1, NCELLS>>>();
    cell_scatter_kernel<<<(NS + 255) / 256, 256>>>();

    // combined weights: WcS = W_s_pre @ W_sg, WcG = W_g_pre @ W_gs
    {
        float* WcS; cudaGetSymbolAddress((void**)&WcS, g_WcS);
        float* WcG; cudaGetSymbolAddress((void**)&WcG, g_WcG);
        gemm_kernel<128, false, false><<<dim3(1, 1), 256>>>(
            W_s_pre, nullptr, W_sg, W_sg, WcS, WcS, 128);
        gemm_kernel<128, false, false><<<dim3(1, 1), 256>>>(
            W_g_pre, nullptr, W_gs, W_gs, WcG, WcG, 128);
    }

    knn_kernel<<<NG / WPB, 32 * WPB>>>(pos_g);

    zero_xsout_kernel<<<(NS * DD / 4 + 255) / 256, 256>>>();

    {
        float* hs; cudaGetSymbolAddress((void**)&hs, g_hs);
        float* ms; cudaGetSymbolAddress((void**)&ms, g_ms);
        float* hg; cudaGetSymbolAddress((void**)&hg, g_hg);
        float* mg; cudaGetSymbolAddress((void**)&mg, g_mg);
        float* WcS; cudaGetSymbolAddress((void**)&WcS, g_WcS);
        float* WcG; cudaGetSymbolAddress((void**)&WcG, g_WcG);
        gemm_kernel<128, false, false><<<dim3((NS + 127) / 128, 2), 256>>>(
            xs, nullptr, W_s_pre, WcS, hs, ms, NS);
        gemm_kernel<128, false, false><<<dim3((NG + 127) / 128, 2), 256>>>(
            xg, nullptr, W_g_pre, WcG, hg, mg, NG);
    }

    scatter_kernel<<<NG, 128>>>();
    gather_kernel<<<NG, 128>>>();

    {
        float* hs; cudaGetSymbolAddress((void**)&hs, g_hs);
        float* hg; cudaGetSymbolAddress((void**)&hg, g_hg);
        float* xso; cudaGetSymbolAddress((void**)&xso, g_xsout);
        float* xgo; cudaGetSymbolAddress((void**)&xgo, g_xgout);
        gemm_kernel<256, true, true><<<dim3((NS + 127) / 128, 1), 256>>>(
            hs, xso, W_s_post, W_s_post, out_s, out_s, NS);
        gemm_kernel<256, true, true><<<dim3((NG + 127) / 128, 1), 256>>>(
            hg, xgo, W_g_post, W_g_post, out_g, out_g, NG);
    }
}